// round 16
// baseline (speedup 1.0000x reference)
#include <cuda_runtime.h>
#include <cuda_fp16.h>
#include <math.h>
#include <stdint.h>

#define Bb 8
#define Ss 1024
#define Dd 768
#define FFf 3072
#define Ee 8
#define KK 2

// ======================= scratch (no allocs allowed) =======================
__device__ __align__(256) __half g_xh[(size_t)Bb * Ss * Dd];       // x fp16
__device__ __align__(256) __half g_w1[(size_t)Ee * FFf * Dd];      // W1^T [E,FF,D] fp16
__device__ __align__(256) __half g_w2[(size_t)Ee * Dd * FFf];      // W2^T [E,D,FF] fp16
__device__ __align__(256) __half g_hh[(size_t)Bb * KK * Ss * FFf]; // topv*gelu(xW1+b1) fp16
__device__ __align__(256) float g_mixp[(size_t)4 * Bb * Ss * Dd];  // 4 partials
__device__ int   g_topi[Bb * KK];
__device__ float g_topv[Bb * KK];

// ======================= PTX helpers (base ISA sm_80-era) =======================
__device__ __forceinline__ uint32_t smem_u32(const void* p) {
    uint32_t a;
    asm("{ .reg .u64 t; cvta.to.shared.u64 t, %1; cvt.u32.u64 %0, t; }"
        : "=r"(a) : "l"(p));
    return a;
}
__device__ __forceinline__ void cp16(uint32_t s, const void* g) {
    asm volatile("cp.async.cg.shared.global [%0], [%1], 16;" :: "r"(s), "l"(g) : "memory");
}
#define CP_COMMIT() asm volatile("cp.async.commit_group;" ::: "memory")
#define CP_WAIT1()  asm volatile("cp.async.wait_group 1;" ::: "memory")
#define CP_WAIT0()  asm volatile("cp.async.wait_group 0;" ::: "memory")

#define LDSM4(r, addr) \
    asm volatile("ldmatrix.sync.aligned.m8n8.x4.shared.b16 {%0,%1,%2,%3}, [%4];" \
        : "=r"((r)[0]), "=r"((r)[1]), "=r"((r)[2]), "=r"((r)[3]) : "r"(addr))

__device__ __forceinline__ void mma16816(float* d, const uint32_t* a, const uint32_t* b) {
    asm volatile(
        "mma.sync.aligned.m16n8k16.row.col.f32.f16.f16.f32 "
        "{%0,%1,%2,%3}, {%4,%5,%6,%7}, {%8,%9}, {%0,%1,%2,%3};"
        : "+f"(d[0]), "+f"(d[1]), "+f"(d[2]), "+f"(d[3])
        : "r"(a[0]), "r"(a[1]), "r"(a[2]), "r"(a[3]), "r"(b[0]), "r"(b[1]));
}

// fast gelu: tanh.approx.f32 (max rel err ~2^-11)
__device__ __forceinline__ float gelu_fast(float v) {
    float u = v * (0.7978845608028654f + 0.035677408136300125f * v * v);
    float t;
    asm("tanh.approx.f32 %0, %1;" : "=f"(t) : "f"(u));
    return 0.5f * v * (1.f + t);
}

// smem tile geometry: 128 rows x 32 fp16, rows padded to 40 halves (80B)
#define ROWB   80
#define ARRB   10240                // 128 * 80
#define STAGE  20480                // 2 arrays (A, B)
#define NSTG   3
#define SMEM_BYTES (NSTG * STAGE)   // 61440

// stage load: A (128x32) + B (128x32)
__device__ __forceinline__ void load_stage(uint32_t sbase,
                                           const __half* A, size_t ldA,
                                           const __half* Bw, size_t ldB,
                                           int tid) {
#pragma unroll
    for (int i = 0; i < 4; i++) {
        int c   = tid + i * 128;
        int row = c >> 2, q = c & 3;
        uint32_t so = (uint32_t)(row * ROWB + q * 16);
        cp16(sbase + so,        A  + (size_t)row * ldA + q * 8);
        cp16(sbase + ARRB + so, Bw + (size_t)row * ldB + q * 8);
    }
}

// compute one K=32 stage, warp tile 64x64: D += A*B (single fp16 MMA path)
__device__ __forceinline__ void compute_stage(uint32_t sbase, int wm, int wn, int lane,
                                              float d[4][8][4]) {
#pragma unroll
    for (int kb = 0; kb < 2; kb++) {
        uint32_t af[4][4];
#pragma unroll
        for (int mt = 0; mt < 4; mt++) {
            int row  = wm * 64 + mt * 16 + (lane & 15);
            int kcol = kb * 16 + (lane >> 4) * 8;
            LDSM4(af[mt], sbase + row * ROWB + kcol * 2);
        }
        int nbase = wn * 64 + ((lane >> 4) & 1) * 8 + (lane & 7);
        int kcol  = kb * 16 + ((lane >> 3) & 1) * 8;
        uint32_t bbase = sbase + ARRB + kcol * 2;

        uint32_t bf[2][2][2];
        {
            uint32_t r[4];
            LDSM4(r, bbase + nbase * ROWB);
            bf[0][0][0] = r[0]; bf[0][0][1] = r[1];
            bf[0][1][0] = r[2]; bf[0][1][1] = r[3];
        }
#pragma unroll
        for (int p = 0; p < 4; p++) {
            int cur = p & 1, nxt = cur ^ 1;
            if (p < 3) {
                uint32_t r[4];
                LDSM4(r, bbase + (nbase + (p + 1) * 16) * ROWB);
                bf[nxt][0][0] = r[0]; bf[nxt][0][1] = r[1];
                bf[nxt][1][0] = r[2]; bf[nxt][1][1] = r[3];
            }
#pragma unroll
            for (int g = 0; g < 2; g++) {
                int nt = 2 * p + g;
#pragma unroll
                for (int mt = 0; mt < 4; mt++)
                    mma16816(d[mt][nt], af[mt], bf[cur][g]);
            }
        }
    }
}

// ======================= merged prep kernel =======================
// blocks [0,8): router   [8, 8+6144): x->fp16   then W1-transpose tiles, W2-transpose tiles
#define NB_ROUTER 8
#define NB_SPLITX (Bb * Ss * Dd / 1024)              // 6144
#define NB_W1     (FFf / 32 * Dd / 32 * Ee)          // 18432
#define NB_W2     (Dd / 32 * FFf / 32 * Ee)          // 18432
#define NB_PREP   (NB_ROUTER + NB_SPLITX + NB_W1 + NB_W2)

__global__ void prep_kernel(const float* __restrict__ x,
                            const float* __restrict__ ts,
                            const float* __restrict__ rw,
                            const float* __restrict__ rb,
                            const float* __restrict__ W1,
                            const float* __restrict__ W2,
                            float* __restrict__ probs_out) {
    __shared__ float sh[1800];
    int bid = blockIdx.x;
    int tid = threadIdx.x;

    if (bid < NB_ROUTER) {
        // ---- router (b = bid) ----
        int b = bid;
        float* feat   = sh;          // [1536]
        float* red    = sh + 1536;   // [256]
        float* logits = sh + 1792;   // [8]
        for (int d = tid; d < Dd; d += 256) {
            float acc = 0.f;
            const float* xb = x + (size_t)b * Ss * Dd + d;
            for (int s = 0; s < Ss; s++) acc += xb[(size_t)s * Dd];
            feat[d]      = acc * (1.0f / Ss);
            feat[Dd + d] = ts[b * Dd + d];
        }
        __syncthreads();
        for (int e = 0; e < Ee; e++) {
            float p = 0.f;
            for (int d = tid; d < 2 * Dd; d += 256) p += feat[d] * rw[d * Ee + e];
            red[tid] = p;
            __syncthreads();
            for (int s = 128; s > 0; s >>= 1) {
                if (tid < s) red[tid] += red[tid + s];
                __syncthreads();
            }
            if (tid == 0) logits[e] = red[0] + rb[e];
            __syncthreads();
        }
        if (tid == 0) {
            float mx = logits[0];
            for (int e = 1; e < Ee; e++) mx = fmaxf(mx, logits[e]);
            float p[Ee], den = 0.f;
            for (int e = 0; e < Ee; e++) { p[e] = expf(logits[e] - mx); den += p[e]; }
            float inv = 1.f / den;
            for (int e = 0; e < Ee; e++) { p[e] *= inv; probs_out[b * Ee + e] = p[e]; }
            int i0 = 0;
            for (int e = 1; e < Ee; e++) if (p[e] > p[i0]) i0 = e;
            int i1 = -1;
            for (int e = 0; e < Ee; e++) {
                if (e == i0) continue;
                if (i1 < 0 || p[e] > p[i1]) i1 = e;
            }
            g_topi[b * KK + 0] = i0;  g_topv[b * KK + 0] = p[i0];
            g_topi[b * KK + 1] = i1;  g_topv[b * KK + 1] = p[i1];
        }
        return;
    }
    bid -= NB_ROUTER;

    if (bid < NB_SPLITX) {
        // ---- x -> fp16 ----
        size_t i = ((size_t)bid * 256 + tid) * 4;
        float4 v = *(const float4*)(x + i);
        __half2 h01 = __halves2half2(__float2half_rn(v.x), __float2half_rn(v.y));
        __half2 h23 = __halves2half2(__float2half_rn(v.z), __float2half_rn(v.w));
        uint2 uh;
        uh.x = *(uint32_t*)&h01; uh.y = *(uint32_t*)&h23;
        *(uint2*)(g_xh + i) = uh;
        return;
    }
    bid -= NB_SPLITX;

    // ---- W transpose+convert: which=0 -> W1, which=1 -> W2 ----
    int which, R, C, tile;
    const float* W;
    __half* th;
    if (bid < NB_W1) { which = 0; R = Dd; C = FFf; tile = bid; W = W1; th = g_w1; }
    else             { which = 1; R = FFf; C = Dd; tile = bid - NB_W1; W = W2; th = g_w2; }
    (void)which;

    int ncx = C / 32;
    int nry = R / 32;
    int e   = tile / (ncx * nry);
    int rem = tile % (ncx * nry);
    int c0  = (rem % ncx) * 32;
    int r0  = (rem / ncx) * 32;

    float (*t)[33] = (float(*)[33])sh;   // 32x33 floats = 4224 B < 1800*4
    int tx = tid & 31, ty = tid >> 5;    // (32, 8)
    const float* Wp = W + (size_t)e * R * C;
#pragma unroll
    for (int i = 0; i < 4; i++) {
        int r = r0 + ty + i * 8;
        t[ty + i * 8][tx] = Wp[(size_t)r * C + c0 + tx];
    }
    __syncthreads();
#pragma unroll
    for (int i = 0; i < 4; i++) {
        int c = c0 + ty + i * 8;
        float v = t[tx][ty + i * 8];
        size_t o = ((size_t)e * C + c) * R + r0 + tx;
        th[o] = __float2half_rn(v);
    }
}

// ======================= GEMM1: h = topv * gelu(x W1 + b1) =======================
// grid (FFf/128, Ss/128, B*K), 128 threads, CTA tile 128x128, warp tile 64x64
__global__ __launch_bounds__(128, 2) void gemm1_mma(const float* __restrict__ b1) {
    extern __shared__ char smraw[];
    uint32_t sb = smem_u32(smraw);

    int tid = threadIdx.x, lane = tid & 31, warp = tid >> 5;
    int wm = warp & 1, wn = warp >> 1;
    int bk = blockIdx.z;
    int b  = bk >> 1;
    int e  = g_topi[bk];
    int s0 = blockIdx.y * 128, f0 = blockIdx.x * 128;

    const __half* A  = g_xh + ((size_t)b * Ss + s0) * Dd;
    const __half* Bw = g_w1 + ((size_t)e * FFf + f0) * Dd;

    float d[4][8][4];
#pragma unroll
    for (int mt = 0; mt < 4; mt++)
#pragma unroll
        for (int nt = 0; nt < 8; nt++)
#pragma unroll
            for (int q = 0; q < 4; q++) d[mt][nt][q] = 0.f;

    const int nk = Dd / 32;    // 24
    load_stage(sb, A, Dd, Bw, Dd, tid);
    CP_COMMIT();
    load_stage(sb + STAGE, A + 32, Dd, Bw + 32, Dd, tid);
    CP_COMMIT();

    for (int ks = 0; ks < nk; ks++) {
        if (ks + 1 < nk) CP_WAIT1(); else CP_WAIT0();
        __syncthreads();
        if (ks + 2 < nk) {
            int kk = (ks + 2) * 32;
            load_stage(sb + ((ks + 2) % NSTG) * STAGE, A + kk, Dd, Bw + kk, Dd, tid);
            CP_COMMIT();
        }
        compute_stage(sb + (ks % NSTG) * STAGE, wm, wn, lane, d);
    }

    // epilogue: + b1, gelu, * topv, store fp16
    const float* b1e = b1 + (size_t)e * FFf + f0;
    float w = g_topv[bk];
    int lrow = lane >> 2;
    int lcol = (lane & 3) * 2;
#pragma unroll
    for (int mt = 0; mt < 4; mt++) {
#pragma unroll
        for (int nt = 0; nt < 8; nt++) {
            int fc = wn * 64 + nt * 8 + lcol;
            float bb0 = b1e[fc];
            float bb1 = b1e[fc + 1];
#pragma unroll
            for (int half_i = 0; half_i < 2; half_i++) {
                int s = s0 + wm * 64 + mt * 16 + lrow + half_i * 8;
                float g0 = w * gelu_fast(d[mt][nt][2 * half_i]     + bb0);
                float g1 = w * gelu_fast(d[mt][nt][2 * half_i + 1] + bb1);
                __half2 hh = __halves2half2(__float2half_rn(g0), __float2half_rn(g1));
                size_t off = ((size_t)bk * Ss + s) * FFf + f0 + fc;
                *(uint32_t*)(g_hh + off) = *(uint32_t*)&hh;
            }
        }
    }
}

// ======================= GEMM2 (expert- and K-split, single fp16) =======================
// grid (Dd/128, Ss/128, B*K*2); z = bk*2 + slice (slice = half of FF)
__global__ __launch_bounds__(128, 2) void gemm2_mma(const float* __restrict__ b2) {
    extern __shared__ char smraw[];
    uint32_t sb = smem_u32(smraw);

    int tid = threadIdx.x, lane = tid & 31, warp = tid >> 5;
    int wm = warp & 1, wn = warp >> 1;
    int z     = blockIdx.z;
    int bk    = z >> 1;
    int slice = z & 1;
    int b  = bk >> 1;
    int e  = g_topi[bk];
    int s0 = blockIdx.y * 128, d0 = blockIdx.x * 128;
    int kbase = slice * (FFf / 2);

    const __half* A  = g_hh + ((size_t)bk * Ss + s0) * FFf + kbase;
    const __half* Bw = g_w2 + ((size_t)e * Dd + d0) * FFf + kbase;

    float d[4][8][4];
#pragma unroll
    for (int mt = 0; mt < 4; mt++)
#pragma unroll
        for (int nt = 0; nt < 8; nt++)
#pragma unroll
            for (int q = 0; q < 4; q++) d[mt][nt][q] = 0.f;

    const int nk = (FFf / 2) / 32;   // 48
    load_stage(sb, A, FFf, Bw, FFf, tid);
    CP_COMMIT();
    load_stage(sb + STAGE, A + 32, FFf, Bw + 32, FFf, tid);
    CP_COMMIT();

    for (int ks = 0; ks < nk; ks++) {
        if (ks + 1 < nk) CP_WAIT1(); else CP_WAIT0();
        __syncthreads();
        if (ks + 2 < nk) {
            int kk = (ks + 2) * 32;
            load_stage(sb + ((ks + 2) % NSTG) * STAGE, A + kk, FFf, Bw + kk, FFf, tid);
            CP_COMMIT();
        }
        compute_stage(sb + (ks % NSTG) * STAGE, wm, wn, lane, d);
    }

    // epilogue: + topv * b2[e] (slice 0 only), write fp32 partial
    float tv = (slice == 0) ? g_topv[bk] : 0.f;
    const float* b2e = b2 + (size_t)e * Dd + d0;
    float* dst = g_mixp + (size_t)((bk & 1) * 2 + slice) * ((size_t)Bb * Ss * Dd);
    int lrow = lane >> 2;
    int lcol = (lane & 3) * 2;
#pragma unroll
    for (int mt = 0; mt < 4; mt++) {
#pragma unroll
        for (int nt = 0; nt < 8; nt++) {
            int nn = wn * 64 + nt * 8 + lcol;
            float bias0 = tv * b2e[nn];
            float bias1 = tv * b2e[nn + 1];
#pragma unroll
            for (int half_i = 0; half_i < 2; half_i++) {
                int s = s0 + wm * 64 + mt * 16 + lrow + half_i * 8;
                float2 o;
                o.x = d[mt][nt][2 * half_i]     + bias0;
                o.y = d[mt][nt][2 * half_i + 1] + bias1;
                *(float2*)(dst + ((size_t)b * Ss + s) * Dd + d0 + nn) = o;
            }
        }
    }
}

// ======================= kernel: out = x + LN(sum of 4 partials) =======================
__global__ void ln_kernel(const float* __restrict__ x,
                          const float* __restrict__ gamma,
                          const float* __restrict__ beta,
                          float* __restrict__ out) {
    int row = blockIdx.x;
    int tid = threadIdx.x;
    const size_t BSD = (size_t)Bb * Ss * Dd;
    const float* m0 = g_mixp + (size_t)row * Dd;
    const float* m1 = m0 + BSD;
    const float* m2 = m1 + BSD;
    const float* m3 = m2 + BSD;

    float v0 = m0[tid]       + m1[tid]       + m2[tid]       + m3[tid];
    float v1 = m0[tid + 256] + m1[tid + 256] + m2[tid + 256] + m3[tid + 256];
    float v2 = m0[tid + 512] + m1[tid + 512] + m2[tid + 512] + m3[tid + 512];
    __shared__ float red[256], red2[256];
    red[tid]  = v0 + v1 + v2;
    red2[tid] = v0 * v0 + v1 * v1 + v2 * v2;
    __syncthreads();
    for (int s = 128; s > 0; s >>= 1) {
        if (tid < s) { red[tid] += red[tid + s]; red2[tid] += red2[tid + s]; }
        __syncthreads();
    }
    __shared__ float smu, sinv;
    if (tid == 0) {
        float mu  = red[0] * (1.0f / Dd);
        float var = red2[0] * (1.0f / Dd) - mu * mu;
        smu = mu; sinv = rsqrtf(var + 1e-5f);
    }
    __syncthreads();
    float mu = smu, inv = sinv;
    const float* xr = x + (size_t)row * Dd;
    float* o = out + (size_t)row * Dd;
    float vv[3] = {v0, v1, v2};
#pragma unroll
    for (int q = 0; q < 3; q++) {
        int dd = tid + q * 256;
        o[dd] = xr[dd] + (vv[q] - mu) * inv * gamma[dd] + beta[dd];
    }
}

// ======================= launch =======================
extern "C" void kernel_launch(void* const* d_in, const int* in_sizes, int n_in,
                              void* d_out, int out_size) {
    const float* x   = (const float*)d_in[0];
    const float* ts  = (const float*)d_in[1];
    const float* W1  = (const float*)d_in[2];
    const float* b1  = (const float*)d_in[3];
    const float* W2  = (const float*)d_in[4];
    const float* b2  = (const float*)d_in[5];
    const float* rw  = (const float*)d_in[6];
    const float* rb  = (const float*)d_in[7];
    const float* gam = (const float*)d_in[8];
    const float* bet = (const float*)d_in[9];

    float* out   = (float*)d_out;
    float* probs = out + (size_t)Bb * Ss * Dd;

    cudaFuncSetAttribute(gemm1_mma, cudaFuncAttributeMaxDynamicSharedMemorySize, SMEM_BYTES);
    cudaFuncSetAttribute(gemm2_mma, cudaFuncAttributeMaxDynamicSharedMemorySize, SMEM_BYTES);

    prep_kernel<<<NB_PREP, 256>>>(x, ts, rw, rb, W1, W2, probs);

    gemm1_mma<<<dim3(FFf / 128, Ss / 128, Bb * KK), 128, SMEM_BYTES>>>(b1);
    gemm2_mma<<<dim3(Dd / 128, Ss / 128, Bb * KK * 2), 128, SMEM_BYTES>>>(b2);

    ln_kernel<<<Bb * Ss, 256>>>(x, gam, bet, out);
}

// round 17
// speedup vs baseline: 1.0026x; 1.0026x over previous
#include <cuda_runtime.h>
#include <cuda_fp16.h>
#include <math.h>
#include <stdint.h>

#define Bb 8
#define Ss 1024
#define Dd 768
#define FFf 3072
#define Ee 8
#define KK 2

// ======================= scratch (no allocs allowed) =======================
__device__ __align__(256) __half g_xh[(size_t)Bb * Ss * Dd];       // x fp16
__device__ __align__(256) __half g_w1[(size_t)Ee * FFf * Dd];      // W1^T [E,FF,D] fp16
__device__ __align__(256) __half g_w2[(size_t)Ee * Dd * FFf];      // W2^T [E,D,FF] fp16
__device__ __align__(256) __half g_hh[(size_t)Bb * KK * Ss * FFf]; // topv*gelu(xW1+b1) fp16
__device__ __align__(256) float g_mixp[(size_t)4 * Bb * Ss * Dd];  // 4 partials
__device__ int   g_topi[Bb * KK];
__device__ float g_topv[Bb * KK];

// ======================= PTX helpers (base ISA sm_80-era) =======================
__device__ __forceinline__ uint32_t smem_u32(const void* p) {
    uint32_t a;
    asm("{ .reg .u64 t; cvta.to.shared.u64 t, %1; cvt.u32.u64 %0, t; }"
        : "=r"(a) : "l"(p));
    return a;
}
__device__ __forceinline__ void cp16(uint32_t s, const void* g) {
    asm volatile("cp.async.cg.shared.global [%0], [%1], 16;" :: "r"(s), "l"(g) : "memory");
}
#define CP_COMMIT() asm volatile("cp.async.commit_group;" ::: "memory")
#define CP_WAIT1()  asm volatile("cp.async.wait_group 1;" ::: "memory")
#define CP_WAIT0()  asm volatile("cp.async.wait_group 0;" ::: "memory")

#define LDSM4(r, addr) \
    asm volatile("ldmatrix.sync.aligned.m8n8.x4.shared.b16 {%0,%1,%2,%3}, [%4];" \
        : "=r"((r)[0]), "=r"((r)[1]), "=r"((r)[2]), "=r"((r)[3]) : "r"(addr))

__device__ __forceinline__ void mma16816(float* d, const uint32_t* a, const uint32_t* b) {
    asm volatile(
        "mma.sync.aligned.m16n8k16.row.col.f32.f16.f16.f32 "
        "{%0,%1,%2,%3}, {%4,%5,%6,%7}, {%8,%9}, {%0,%1,%2,%3};"
        : "+f"(d[0]), "+f"(d[1]), "+f"(d[2]), "+f"(d[3])
        : "r"(a[0]), "r"(a[1]), "r"(a[2]), "r"(a[3]), "r"(b[0]), "r"(b[1]));
}

// fast gelu: tanh.approx.f32 (max rel err ~2^-11)
__device__ __forceinline__ float gelu_fast(float v) {
    float u = v * (0.7978845608028654f + 0.035677408136300125f * v * v);
    float t;
    asm("tanh.approx.f32 %0, %1;" : "=f"(t) : "f"(u));
    return 0.5f * v * (1.f + t);
}

// smem tile geometry: 128 rows x 32 fp16, rows padded to 40 halves (80B)
#define ROWB   80
#define ARRB   10240                // 128 * 80
#define STAGE  20480                // 2 arrays (A, B)
#define NSTG   3
#define SMEM_BYTES (NSTG * STAGE)   // 61440

// stage load: A (128x32) + B (128x32)
__device__ __forceinline__ void load_stage(uint32_t sbase,
                                           const __half* A, size_t ldA,
                                           const __half* Bw, size_t ldB,
                                           int tid) {
#pragma unroll
    for (int i = 0; i < 4; i++) {
        int c   = tid + i * 128;
        int row = c >> 2, q = c & 3;
        uint32_t so = (uint32_t)(row * ROWB + q * 16);
        cp16(sbase + so,        A  + (size_t)row * ldA + q * 8);
        cp16(sbase + ARRB + so, Bw + (size_t)row * ldB + q * 8);
    }
}

// compute one K=32 stage, warp tile 64x64: D += A*B (single fp16 MMA path)
__device__ __forceinline__ void compute_stage(uint32_t sbase, int wm, int wn, int lane,
                                              float d[4][8][4]) {
#pragma unroll
    for (int kb = 0; kb < 2; kb++) {
        uint32_t af[4][4];
#pragma unroll
        for (int mt = 0; mt < 4; mt++) {
            int row  = wm * 64 + mt * 16 + (lane & 15);
            int kcol = kb * 16 + (lane >> 4) * 8;
            LDSM4(af[mt], sbase + row * ROWB + kcol * 2);
        }
        int nbase = wn * 64 + ((lane >> 4) & 1) * 8 + (lane & 7);
        int kcol  = kb * 16 + ((lane >> 3) & 1) * 8;
        uint32_t bbase = sbase + ARRB + kcol * 2;

        uint32_t bf[2][2][2];
        {
            uint32_t r[4];
            LDSM4(r, bbase + nbase * ROWB);
            bf[0][0][0] = r[0]; bf[0][0][1] = r[1];
            bf[0][1][0] = r[2]; bf[0][1][1] = r[3];
        }
#pragma unroll
        for (int p = 0; p < 4; p++) {
            int cur = p & 1, nxt = cur ^ 1;
            if (p < 3) {
                uint32_t r[4];
                LDSM4(r, bbase + (nbase + (p + 1) * 16) * ROWB);
                bf[nxt][0][0] = r[0]; bf[nxt][0][1] = r[1];
                bf[nxt][1][0] = r[2]; bf[nxt][1][1] = r[3];
            }
#pragma unroll
            for (int g = 0; g < 2; g++) {
                int nt = 2 * p + g;
#pragma unroll
                for (int mt = 0; mt < 4; mt++)
                    mma16816(d[mt][nt], af[mt], bf[cur][g]);
            }
        }
    }
}

// ======================= merged prep kernel =======================
// blocks [0,8): router   [8, 8+6144): x->fp16   then W1-transpose tiles, W2-transpose tiles
#define NB_ROUTER 8
#define NB_SPLITX (Bb * Ss * Dd / 1024)              // 6144
#define NB_W1     (FFf / 32 * Dd / 32 * Ee)          // 18432
#define NB_W2     (Dd / 32 * FFf / 32 * Ee)          // 18432
#define NB_PREP   (NB_ROUTER + NB_SPLITX + NB_W1 + NB_W2)

__global__ void prep_kernel(const float* __restrict__ x,
                            const float* __restrict__ ts,
                            const float* __restrict__ rw,
                            const float* __restrict__ rb,
                            const float* __restrict__ W1,
                            const float* __restrict__ W2,
                            float* __restrict__ probs_out) {
    __shared__ float sh[1800];
    int bid = blockIdx.x;
    int tid = threadIdx.x;

    if (bid < NB_ROUTER) {
        // ---- router (b = bid) ----
        int b = bid;
        float* feat   = sh;          // [1536]
        float* red    = sh + 1536;   // [256]
        float* logits = sh + 1792;   // [8]
        for (int d = tid; d < Dd; d += 256) {
            float acc = 0.f;
            const float* xb = x + (size_t)b * Ss * Dd + d;
            for (int s = 0; s < Ss; s++) acc += xb[(size_t)s * Dd];
            feat[d]      = acc * (1.0f / Ss);
            feat[Dd + d] = ts[b * Dd + d];
        }
        __syncthreads();
        for (int e = 0; e < Ee; e++) {
            float p = 0.f;
            for (int d = tid; d < 2 * Dd; d += 256) p += feat[d] * rw[d * Ee + e];
            red[tid] = p;
            __syncthreads();
            for (int s = 128; s > 0; s >>= 1) {
                if (tid < s) red[tid] += red[tid + s];
                __syncthreads();
            }
            if (tid == 0) logits[e] = red[0] + rb[e];
            __syncthreads();
        }
        if (tid == 0) {
            float mx = logits[0];
            for (int e = 1; e < Ee; e++) mx = fmaxf(mx, logits[e]);
            float p[Ee], den = 0.f;
            for (int e = 0; e < Ee; e++) { p[e] = expf(logits[e] - mx); den += p[e]; }
            float inv = 1.f / den;
            for (int e = 0; e < Ee; e++) { p[e] *= inv; probs_out[b * Ee + e] = p[e]; }
            int i0 = 0;
            for (int e = 1; e < Ee; e++) if (p[e] > p[i0]) i0 = e;
            int i1 = -1;
            for (int e = 0; e < Ee; e++) {
                if (e == i0) continue;
                if (i1 < 0 || p[e] > p[i1]) i1 = e;
            }
            g_topi[b * KK + 0] = i0;  g_topv[b * KK + 0] = p[i0];
            g_topi[b * KK + 1] = i1;  g_topv[b * KK + 1] = p[i1];
        }
        return;
    }
    bid -= NB_ROUTER;

    if (bid < NB_SPLITX) {
        // ---- x -> fp16 ----
        size_t i = ((size_t)bid * 256 + tid) * 4;
        float4 v = *(const float4*)(x + i);
        __half2 h01 = __halves2half2(__float2half_rn(v.x), __float2half_rn(v.y));
        __half2 h23 = __halves2half2(__float2half_rn(v.z), __float2half_rn(v.w));
        uint2 uh;
        uh.x = *(uint32_t*)&h01; uh.y = *(uint32_t*)&h23;
        *(uint2*)(g_xh + i) = uh;
        return;
    }
    bid -= NB_SPLITX;

    // ---- W transpose+convert: which=0 -> W1, which=1 -> W2 ----
    int which, R, C, tile;
    const float* W;
    __half* th;
    if (bid < NB_W1) { which = 0; R = Dd; C = FFf; tile = bid; W = W1; th = g_w1; }
    else             { which = 1; R = FFf; C = Dd; tile = bid - NB_W1; W = W2; th = g_w2; }
    (void)which;

    int ncx = C / 32;
    int nry = R / 32;
    int e   = tile / (ncx * nry);
    int rem = tile % (ncx * nry);
    int c0  = (rem % ncx) * 32;
    int r0  = (rem / ncx) * 32;

    float (*t)[33] = (float(*)[33])sh;   // 32x33 floats = 4224 B < 1800*4
    int tx = tid & 31, ty = tid >> 5;    // (32, 8)
    const float* Wp = W + (size_t)e * R * C;
#pragma unroll
    for (int i = 0; i < 4; i++) {
        int r = r0 + ty + i * 8;
        t[ty + i * 8][tx] = Wp[(size_t)r * C + c0 + tx];
    }
    __syncthreads();
#pragma unroll
    for (int i = 0; i < 4; i++) {
        int c = c0 + ty + i * 8;
        float v = t[tx][ty + i * 8];
        size_t o = ((size_t)e * C + c) * R + r0 + tx;
        th[o] = __float2half_rn(v);
    }
}

// ======================= GEMM1: h = topv * gelu(x W1 + b1) =======================
// grid (FFf/128, Ss/128, B*K), 128 threads, CTA tile 128x128, warp tile 64x64
__global__ __launch_bounds__(128, 2) void gemm1_mma(const float* __restrict__ b1) {
    extern __shared__ char smraw[];
    uint32_t sb = smem_u32(smraw);

    int tid = threadIdx.x, lane = tid & 31, warp = tid >> 5;
    int wm = warp & 1, wn = warp >> 1;
    int bk = blockIdx.z;
    int b  = bk >> 1;
    int e  = g_topi[bk];
    int s0 = blockIdx.y * 128, f0 = blockIdx.x * 128;

    const __half* A  = g_xh + ((size_t)b * Ss + s0) * Dd;
    const __half* Bw = g_w1 + ((size_t)e * FFf + f0) * Dd;

    float d[4][8][4];
#pragma unroll
    for (int mt = 0; mt < 4; mt++)
#pragma unroll
        for (int nt = 0; nt < 8; nt++)
#pragma unroll
            for (int q = 0; q < 4; q++) d[mt][nt][q] = 0.f;

    const int nk = Dd / 32;    // 24
    load_stage(sb, A, Dd, Bw, Dd, tid);
    CP_COMMIT();
    load_stage(sb + STAGE, A + 32, Dd, Bw + 32, Dd, tid);
    CP_COMMIT();

    for (int ks = 0; ks < nk; ks++) {
        if (ks + 1 < nk) CP_WAIT1(); else CP_WAIT0();
        __syncthreads();
        if (ks + 2 < nk) {
            int kk = (ks + 2) * 32;
            load_stage(sb + ((ks + 2) % NSTG) * STAGE, A + kk, Dd, Bw + kk, Dd, tid);
            CP_COMMIT();
        }
        compute_stage(sb + (ks % NSTG) * STAGE, wm, wn, lane, d);
    }

    // epilogue: + b1, gelu, * topv, store fp16
    const float* b1e = b1 + (size_t)e * FFf + f0;
    float w = g_topv[bk];
    int lrow = lane >> 2;
    int lcol = (lane & 3) * 2;
#pragma unroll
    for (int mt = 0; mt < 4; mt++) {
#pragma unroll
        for (int nt = 0; nt < 8; nt++) {
            int fc = wn * 64 + nt * 8 + lcol;
            float bb0 = b1e[fc];
            float bb1 = b1e[fc + 1];
#pragma unroll
            for (int half_i = 0; half_i < 2; half_i++) {
                int s = s0 + wm * 64 + mt * 16 + lrow + half_i * 8;
                float g0 = w * gelu_fast(d[mt][nt][2 * half_i]     + bb0);
                float g1 = w * gelu_fast(d[mt][nt][2 * half_i + 1] + bb1);
                __half2 hh = __halves2half2(__float2half_rn(g0), __float2half_rn(g1));
                size_t off = ((size_t)bk * Ss + s) * FFf + f0 + fc;
                *(uint32_t*)(g_hh + off) = *(uint32_t*)&hh;
            }
        }
    }
}

// ======================= GEMM2 (expert- and K-split, single fp16) =======================
// grid (Dd/128, Ss/128, B*K*2); z = bk*2 + slice (slice = half of FF)
__global__ __launch_bounds__(128, 2) void gemm2_mma(const float* __restrict__ b2) {
    extern __shared__ char smraw[];
    uint32_t sb = smem_u32(smraw);

    int tid = threadIdx.x, lane = tid & 31, warp = tid >> 5;
    int wm = warp & 1, wn = warp >> 1;
    int z     = blockIdx.z;
    int bk    = z >> 1;
    int slice = z & 1;
    int b  = bk >> 1;
    int e  = g_topi[bk];
    int s0 = blockIdx.y * 128, d0 = blockIdx.x * 128;
    int kbase = slice * (FFf / 2);

    const __half* A  = g_hh + ((size_t)bk * Ss + s0) * FFf + kbase;
    const __half* Bw = g_w2 + ((size_t)e * Dd + d0) * FFf + kbase;

    float d[4][8][4];
#pragma unroll
    for (int mt = 0; mt < 4; mt++)
#pragma unroll
        for (int nt = 0; nt < 8; nt++)
#pragma unroll
            for (int q = 0; q < 4; q++) d[mt][nt][q] = 0.f;

    const int nk = (FFf / 2) / 32;   // 48
    load_stage(sb, A, FFf, Bw, FFf, tid);
    CP_COMMIT();
    load_stage(sb + STAGE, A + 32, FFf, Bw + 32, FFf, tid);
    CP_COMMIT();

    for (int ks = 0; ks < nk; ks++) {
        if (ks + 1 < nk) CP_WAIT1(); else CP_WAIT0();
        __syncthreads();
        if (ks + 2 < nk) {
            int kk = (ks + 2) * 32;
            load_stage(sb + ((ks + 2) % NSTG) * STAGE, A + kk, FFf, Bw + kk, FFf, tid);
            CP_COMMIT();
        }
        compute_stage(sb + (ks % NSTG) * STAGE, wm, wn, lane, d);
    }

    // epilogue: + topv * b2[e] (slice 0 only), write fp32 partial
    float tv = (slice == 0) ? g_topv[bk] : 0.f;
    const float* b2e = b2 + (size_t)e * Dd + d0;
    float* dst = g_mixp + (size_t)((bk & 1) * 2 + slice) * ((size_t)Bb * Ss * Dd);
    int lrow = lane >> 2;
    int lcol = (lane & 3) * 2;
#pragma unroll
    for (int mt = 0; mt < 4; mt++) {
#pragma unroll
        for (int nt = 0; nt < 8; nt++) {
            int nn = wn * 64 + nt * 8 + lcol;
            float bias0 = tv * b2e[nn];
            float bias1 = tv * b2e[nn + 1];
#pragma unroll
            for (int half_i = 0; half_i < 2; half_i++) {
                int s = s0 + wm * 64 + mt * 16 + lrow + half_i * 8;
                float2 o;
                o.x = d[mt][nt][2 * half_i]     + bias0;
                o.y = d[mt][nt][2 * half_i + 1] + bias1;
                *(float2*)(dst + ((size_t)b * Ss + s) * Dd + d0 + nn) = o;
            }
        }
    }
}

// ======================= kernel: out = x + LN(sum of 4 partials) =======================
__global__ void ln_kernel(const float* __restrict__ x,
                          const float* __restrict__ gamma,
                          const float* __restrict__ beta,
                          float* __restrict__ out) {
    int row = blockIdx.x;
    int tid = threadIdx.x;
    const size_t BSD = (size_t)Bb * Ss * Dd;
    const float* m0 = g_mixp + (size_t)row * Dd;
    const float* m1 = m0 + BSD;
    const float* m2 = m1 + BSD;
    const float* m3 = m2 + BSD;

    float v0 = m0[tid]       + m1[tid]       + m2[tid]       + m3[tid];
    float v1 = m0[tid + 256] + m1[tid + 256] + m2[tid + 256] + m3[tid + 256];
    float v2 = m0[tid + 512] + m1[tid + 512] + m2[tid + 512] + m3[tid + 512];
    __shared__ float red[256], red2[256];
    red[tid]  = v0 + v1 + v2;
    red2[tid] = v0 * v0 + v1 * v1 + v2 * v2;
    __syncthreads();
    for (int s = 128; s > 0; s >>= 1) {
        if (tid < s) { red[tid] += red[tid + s]; red2[tid] += red2[tid + s]; }
        __syncthreads();
    }
    __shared__ float smu, sinv;
    if (tid == 0) {
        float mu  = red[0] * (1.0f / Dd);
        float var = red2[0] * (1.0f / Dd) - mu * mu;
        smu = mu; sinv = rsqrtf(var + 1e-5f);
    }
    __syncthreads();
    float mu = smu, inv = sinv;
    const float* xr = x + (size_t)row * Dd;
    float* o = out + (size_t)row * Dd;
    float vv[3] = {v0, v1, v2};
#pragma unroll
    for (int q = 0; q < 3; q++) {
        int dd = tid + q * 256;
        o[dd] = xr[dd] + (vv[q] - mu) * inv * gamma[dd] + beta[dd];
    }
}

// ======================= launch =======================
extern "C" void kernel_launch(void* const* d_in, const int* in_sizes, int n_in,
                              void* d_out, int out_size) {
    const float* x   = (const float*)d_in[0];
    const float* ts  = (const float*)d_in[1];
    const float* W1  = (const float*)d_in[2];
    const float* b1  = (const float*)d_in[3];
    const float* W2  = (const float*)d_in[4];
    const float* b2  = (const float*)d_in[5];
    const float* rw  = (const float*)d_in[6];
    const float* rb  = (const float*)d_in[7];
    const float* gam = (const float*)d_in[8];
    const float* bet = (const float*)d_in[9];

    float* out   = (float*)d_out;
    float* probs = out + (size_t)Bb * Ss * Dd;

    cudaFuncSetAttribute(gemm1_mma, cudaFuncAttributeMaxDynamicSharedMemorySize, SMEM_BYTES);
    cudaFuncSetAttribute(gemm2_mma, cudaFuncAttributeMaxDynamicSharedMemorySize, SMEM_BYTES);

    prep_kernel<<<NB_PREP, 256>>>(x, ts, rw, rb, W1, W2, probs);

    gemm1_mma<<<dim3(FFf / 128, Ss / 128, Bb * KK), 128, SMEM_BYTES>>>(b1);
    gemm2_mma<<<dim3(Dd / 128, Ss / 128, Bb * KK * 2), 128, SMEM_BYTES>>>(b2);

    ln_kernel<<<Bb * Ss, 256>>>(x, gam, bet, out);
}